// round 8
// baseline (speedup 1.0000x reference)
#include <cuda_runtime.h>
#include <cuda_bf16.h>
#include <math.h>

#define N_NODES   100000
#define N_EDGES   1600000
#define FEAT      128
#define N_GRAPHS  512
#define N_CLASSES 10

#define SCAN_ELEMS 512
#define SCAN_NBLK  ((N_NODES + SCAN_ELEMS - 1) / SCAN_ELEMS)   // 196

// ---------------- scratch (device globals; referenced ONLY from device code) --
__device__ int   g_deg[N_NODES];
__device__ int   g_off[N_NODES + 1];
__device__ int   g_cur[N_NODES];
__device__ int   g_csr[N_EDGES];
__device__ float g_cnt[N_NODES];
__device__ int   g_end[N_GRAPHS];
__device__ int   g_bsum[SCAN_NBLK];
__device__ int   g_bpre[SCAN_NBLK];

__device__ float g_hA[N_NODES * FEAT];
__device__ float g_hB[N_NODES * FEAT];
__device__ float g_gate[N_NODES];

// ---------------- helpers ----------------
__device__ __forceinline__ float tf32r(float x) {
    unsigned r;
    asm("cvt.rna.tf32.f32 %0, %1;" : "=r"(r) : "f"(x));
    return __uint_as_float(r);
}
__device__ __forceinline__ const float* sel_buf(int sel, const float* xext) {
    return sel == 0 ? xext : (sel == 1 ? (const float*)g_hA : (const float*)g_hB);
}
__device__ __forceinline__ void mma_tf32(float* d, const unsigned* a, const unsigned* b) {
    asm volatile(
        "mma.sync.aligned.m16n8k8.row.col.f32.tf32.tf32.f32 "
        "{%0,%1,%2,%3}, {%4,%5,%6,%7}, {%8,%9}, {%0,%1,%2,%3};"
        : "+f"(d[0]), "+f"(d[1]), "+f"(d[2]), "+f"(d[3])
        : "r"(a[0]), "r"(a[1]), "r"(a[2]), "r"(a[3]), "r"(b[0]), "r"(b[1]));
}
__device__ __forceinline__ void bar_arrive(int id) {
    asm volatile("bar.arrive %0, 256;" :: "r"(id));
}
__device__ __forceinline__ void bar_wait(int id) {
    asm volatile("bar.sync %0, 256;" :: "r"(id));
}

// ---------------- init: zero degrees + graph boundaries ----------------------
__global__ void k_init(const int* __restrict__ batch) {
    int i = blockIdx.x * blockDim.x + threadIdx.x;
    if (i >= N_NODES) return;
    g_deg[i] = 0;
    int b  = batch[i];
    int bn = (i + 1 < N_NODES) ? batch[i + 1] : N_GRAPHS;
    if (i == 0)
        for (int g = 0; g < b; g++) g_end[g] = 0;
    for (int g = b; g < bn; g++) g_end[g] = i + 1;
}

// ---------------- CSR build (split layout: src=ei[0..E), dst=ei[E..2E)) ------
__global__ void k_hist(const int* __restrict__ ei) {
    int e = blockIdx.x * blockDim.x + threadIdx.x;
    if (e < N_EDGES) atomicAdd(&g_deg[ei[N_EDGES + e]], 1);
}

// parallel 3-phase exclusive scan of g_deg -> g_off/g_cur/g_cnt
__global__ void k_scan_a() {
    int b = blockIdx.x, t = threadIdx.x;
    int i0 = b * SCAN_ELEMS + t * 2;
    int d0 = (i0 < N_NODES) ? g_deg[i0] : 0;
    int d1 = (i0 + 1 < N_NODES) ? g_deg[i0 + 1] : 0;
    __shared__ int sh[256];
    sh[t] = d0 + d1;
    __syncthreads();
    for (int s = 128; s > 0; s >>= 1) {
        if (t < s) sh[t] += sh[t + s];
        __syncthreads();
    }
    if (t == 0) g_bsum[b] = sh[0];
}
__global__ void k_scan_b() {
    int t = threadIdx.x;
    __shared__ int sh[256];
    int v = (t < SCAN_NBLK) ? g_bsum[t] : 0;
    sh[t] = v;
    __syncthreads();
    for (int d = 1; d < 256; d <<= 1) {
        int x = (t >= d) ? sh[t - d] : 0;
        __syncthreads();
        sh[t] += x;
        __syncthreads();
    }
    if (t < SCAN_NBLK) g_bpre[t] = sh[t] - v;   // exclusive
}
__global__ void k_scan_c() {
    int b = blockIdx.x, t = threadIdx.x;
    int i0 = b * SCAN_ELEMS + t * 2;
    int d0 = (i0 < N_NODES) ? g_deg[i0] : 0;
    int d1 = (i0 + 1 < N_NODES) ? g_deg[i0 + 1] : 0;
    __shared__ int sh[256];
    int v = d0 + d1;
    sh[t] = v;
    __syncthreads();
    for (int d = 1; d < 256; d <<= 1) {
        int x = (t >= d) ? sh[t - d] : 0;
        __syncthreads();
        sh[t] += x;
        __syncthreads();
    }
    int pre = g_bpre[b] + sh[t] - v;
    if (i0 < N_NODES) {
        g_off[i0] = pre; g_cur[i0] = pre;
        g_cnt[i0] = fmaxf((float)d0, 1.0f);
    }
    if (i0 + 1 < N_NODES) {
        g_off[i0 + 1] = pre + d0; g_cur[i0 + 1] = pre + d0;
        g_cnt[i0 + 1] = fmaxf((float)d1, 1.0f);
    }
    if (b == 0 && t == 0) g_off[N_NODES] = N_EDGES;
}

__global__ void k_scatter(const int* __restrict__ ei) {
    int e = blockIdx.x * blockDim.x + threadIdx.x;
    if (e < N_EDGES) {
        int pos = atomicAdd(&g_cur[ei[N_EDGES + e]], 1);
        g_csr[pos] = ei[e];
    }
}

// ---------------- fused layer: out = relu(mean(X)@W1 + X@W2 + bias) ----------
// Warp-specialized: warps 0-3 produce A chunks (gather-mean / direct) + B chunks
// into double-buffered SMEM; warps 4-7 consume with mma.m16n8k8.tf32.
#define TILE_M 128
#define APITCH 36            // bank = 4*row+col  (conflict-free frags)
#define BPITCH 136           // bank = 8*k+n      (conflict-free frags)
#define AS_SZ  (TILE_M * APITCH)         // 4608 floats
#define BS_SZ  (32 * BPITCH)             // 4352 floats
#define LAYER_SMEM ((2 * AS_SZ + 2 * BS_SZ) * 4)   // 71680 bytes

__global__ __launch_bounds__(256) void k_layer(
    const float* __restrict__ xext,
    const float* __restrict__ W1, const float* __restrict__ W2,
    const float* __restrict__ bias, int sel, int nrows)
{
    const float* __restrict__ X = sel_buf(sel, xext);   // layer input (gather + direct)
    float* __restrict__ out = (sel == 1) ? g_hB : g_hA;

    extern __shared__ float sm[];
    float* AsB[2] = { sm, sm + AS_SZ };
    float* BsB[2] = { sm + 2 * AS_SZ, sm + 2 * AS_SZ + BS_SZ };

    int row0 = blockIdx.x * TILE_M;
    int tid  = threadIdx.x;
    int lane = tid & 31;
    int wid  = tid >> 5;

    if (wid < 4) {
        // ================= PRODUCER (warps 0-3) =================
        int rb = wid * 32;
        for (int c = 0; c < 8; c++) {
            int buf = c & 1;
            if (c >= 2) bar_wait(3 + buf);           // wait EMPTY[buf]
            const float* __restrict__ W = (c < 4) ? W1 : W2;
            int k0 = (c & 3) * 32;
            float* As = AsB[buf];
            float* Bs = BsB[buf];

            // ---- stage B chunk [32 x 128] (128 producer threads, 32 floats each)
            {
                int k  = tid >> 2;
                int cb = (tid & 3) * 32;
                const float* wr = W + (size_t)(k0 + k) * FEAT + cb;
                float* br = Bs + k * BPITCH + cb;
#pragma unroll
                for (int i = 0; i < 8; i++) {
                    float4 v = *(const float4*)(wr + i * 4);
                    br[i * 4 + 0] = tf32r(v.x);
                    br[i * 4 + 1] = tf32r(v.y);
                    br[i * 4 + 2] = tf32r(v.z);
                    br[i * 4 + 3] = tf32r(v.w);
                }
            }
            // ---- stage A chunk [128 x 32]
            if (c < 4) {
                // gather-mean: 8 rows in flight per warp pass (MLP 8)
                for (int g = 0; g < 4; g++) {
                    int r8 = rb + g * 8;
                    float acc[8];
                    int s[8], len[8];
#pragma unroll
                    for (int q = 0; q < 8; q++) {
                        acc[q] = 0.0f;
                        int grow = row0 + r8 + q;
                        if (grow < nrows) {
                            s[q]   = __ldg(&g_off[grow]);
                            len[q] = __ldg(&g_off[grow + 1]) - s[q];
                        } else { s[q] = 0; len[q] = 0; }
                    }
                    int mx = 0;
#pragma unroll
                    for (int q = 0; q < 8; q++) mx = max(mx, len[q]);
                    for (int j = 0; j < mx; j++) {
#pragma unroll
                        for (int q = 0; q < 8; q++) {
                            if (j < len[q]) {
                                int n = __ldg(&g_csr[s[q] + j]);
                                acc[q] += __ldg(&X[(size_t)n * FEAT + k0 + lane]);
                            }
                        }
                    }
#pragma unroll
                    for (int q = 0; q < 8; q++) {
                        int grow = row0 + r8 + q;
                        float v = 0.0f;
                        if (grow < nrows) v = acc[q] / g_cnt[grow];
                        As[(r8 + q) * APITCH + lane] = tf32r(v);
                    }
                }
            } else {
                // direct copy of X rows
#pragma unroll 4
                for (int rr = 0; rr < 32; rr++) {
                    int r = rb + rr, grow = row0 + r;
                    float v = (grow < nrows)
                        ? __ldg(&X[(size_t)grow * FEAT + k0 + lane]) : 0.0f;
                    As[r * APITCH + lane] = tf32r(v);
                }
            }
            bar_arrive(1 + buf);                     // signal FULL[buf]
        }
    } else {
        // ================= CONSUMER (warps 4-7) =================
        int cw = wid - 4;                            // rows cw*32 .. +31, all 128 cols
        float d[2][16][4];
#pragma unroll
        for (int mt = 0; mt < 2; mt++)
#pragma unroll
            for (int nt = 0; nt < 16; nt++)
#pragma unroll
                for (int k = 0; k < 4; k++) d[mt][nt][k] = 0.0f;

        for (int c = 0; c < 8; c++) {
            int buf = c & 1;
            bar_wait(1 + buf);                       // wait FULL[buf]
            const float* As = AsB[buf];
            const float* Bs = BsB[buf];
#pragma unroll
            for (int ks = 0; ks < 4; ks++) {
                unsigned a[2][4];
                int acol = ks * 8 + (lane & 3);
                int arow = cw * 32 + (lane >> 2);
#pragma unroll
                for (int mt = 0; mt < 2; mt++) {
                    int r0 = arow + mt * 16;
                    a[mt][0] = __float_as_uint(As[r0 * APITCH + acol]);
                    a[mt][1] = __float_as_uint(As[(r0 + 8) * APITCH + acol]);
                    a[mt][2] = __float_as_uint(As[r0 * APITCH + acol + 4]);
                    a[mt][3] = __float_as_uint(As[(r0 + 8) * APITCH + acol + 4]);
                }
                int bk = ks * 8 + (lane & 3);
                int bn = (lane >> 2);
#pragma unroll
                for (int nt = 0; nt < 16; nt++) {
                    unsigned b[2];
                    b[0] = __float_as_uint(Bs[bk * BPITCH + bn + nt * 8]);
                    b[1] = __float_as_uint(Bs[(bk + 4) * BPITCH + bn + nt * 8]);
                    mma_tf32(d[0][nt], a[0], b);
                    mma_tf32(d[1][nt], a[1], b);
                }
            }
            bar_arrive(3 + buf);                     // signal EMPTY[buf]
        }

        // ---- epilogue: bias + relu, float2 stores ----
        int rbase = row0 + cw * 32 + (lane >> 2);
        int cbase = (lane & 3) * 2;
#pragma unroll
        for (int nt = 0; nt < 16; nt++) {
            int col = cbase + nt * 8;
            float bv0 = __ldg(&bias[col]);
            float bv1 = __ldg(&bias[col + 1]);
#pragma unroll
            for (int mt = 0; mt < 2; mt++) {
                int r0 = rbase + mt * 16;
                if (r0 < nrows) {
                    float2 o;
                    o.x = fmaxf(d[mt][nt][0] + bv0, 0.0f);
                    o.y = fmaxf(d[mt][nt][1] + bv1, 0.0f);
                    *(float2*)(out + (size_t)r0 * FEAT + col) = o;
                }
                int r1 = r0 + 8;
                if (r1 < nrows) {
                    float2 o;
                    o.x = fmaxf(d[mt][nt][2] + bv0, 0.0f);
                    o.y = fmaxf(d[mt][nt][3] + bv1, 0.0f);
                    *(float2*)(out + (size_t)r1 * FEAT + col) = o;
                }
            }
        }
    }
}

// ---------------- fused attention pooling + MLP head (1 block / graph) -------
__global__ __launch_bounds__(128) void k_attnpool(
    const float* __restrict__ gate_w, const float* __restrict__ gate_b,
    const float* __restrict__ lin1_w, const float* __restrict__ lin1_b,
    const float* __restrict__ lin2_w, const float* __restrict__ lin2_b,
    float* __restrict__ out)
{
    int g  = blockIdx.x;
    int lo = (g == 0) ? 0 : g_end[g - 1];
    int hi = g_end[g];
    int t = threadIdx.x, warp = t >> 5, lane = t & 31;

    __shared__ float red4[4];
    __shared__ float s_m, s_s;
    __shared__ float sp[FEAT];
    __shared__ float so[FEAT];
    __shared__ float lg[N_CLASSES];

    // ---- pass 1: gate per node + block max ----
    float4 wv = *(const float4*)(gate_w + lane * 4);
    float gb = __ldg(&gate_b[0]);
    float lmax = -1e30f;
    for (int node = lo + warp; node < hi; node += 4) {
        float4 hv = *(const float4*)(g_hA + (size_t)node * FEAT + lane * 4);
        float s = hv.x * wv.x + hv.y * wv.y + hv.z * wv.z + hv.w * wv.w;
#pragma unroll
        for (int d = 16; d > 0; d >>= 1) s += __shfl_xor_sync(0xFFFFFFFFu, s, d);
        s += gb;
        if (lane == 0) g_gate[node] = s;
        lmax = fmaxf(lmax, s);
    }
    if (lane == 0) red4[warp] = lmax;
    __syncthreads();
    if (t == 0)
        s_m = fmaxf(fmaxf(red4[0], red4[1]), fmaxf(red4[2], red4[3]));
    __syncthreads();
    float m = s_m;

    // ---- pass 2: exp + sum ----
    float part = 0.0f;
    for (int node = lo + t; node < hi; node += 128) {
        float e = expf(g_gate[node] - m);
        g_gate[node] = e;
        part += e;
    }
#pragma unroll
    for (int d = 16; d > 0; d >>= 1) part += __shfl_xor_sync(0xFFFFFFFFu, part, d);
    if (lane == 0) red4[warp] = part;
    __syncthreads();
    if (t == 0) s_s = red4[0] + red4[1] + red4[2] + red4[3];
    __syncthreads();
    float s = s_s;
    float invs = (s > 0.0f) ? 1.0f / s : 0.0f;

    // ---- pass 3: weighted feature sum (thread t owns feature t) ----
    float acc = 0.0f;
#pragma unroll 4
    for (int node = lo; node < hi; node++)
        acc += g_gate[node] * g_hA[(size_t)node * FEAT + t];
    sp[t] = acc * invs;
    __syncthreads();

    // ---- head: relu(lin1) -> lin2 -> log_softmax ----
    float h1 = lin1_b[t];
#pragma unroll 8
    for (int k = 0; k < FEAT; k++)
        h1 = fmaf(sp[k], lin1_w[(size_t)k * FEAT + t], h1);
    so[t] = fmaxf(h1, 0.0f);
    __syncthreads();

    if (t < N_CLASSES) {
        float a = lin2_b[t];
#pragma unroll 8
        for (int k = 0; k < FEAT; k++)
            a = fmaf(so[k], lin2_w[(size_t)k * N_CLASSES + t], a);
        lg[t] = a;
    }
    __syncthreads();

    if (t == 0) {
        float mx = lg[0];
#pragma unroll
        for (int j = 1; j < N_CLASSES; j++) mx = fmaxf(mx, lg[j]);
        float se = 0.0f;
#pragma unroll
        for (int j = 0; j < N_CLASSES; j++) se += expf(lg[j] - mx);
        float l = logf(se);
#pragma unroll
        for (int j = 0; j < N_CLASSES; j++)
            out[(size_t)g * N_CLASSES + j] = lg[j] - mx - l;
    }
}

// ---------------- launch ----------------
extern "C" void kernel_launch(void* const* d_in, const int* in_sizes, int n_in,
                              void* d_out, int out_size) {
    const float* x      = (const float*)d_in[0];
    const int*   ei     = (const int*)  d_in[1];
    const int*   batch  = (const int*)  d_in[2];
    const float* w1l = (const float*)d_in[3];
    const float* b1  = (const float*)d_in[4];
    const float* w1r = (const float*)d_in[5];
    const float* w2l = (const float*)d_in[6];
    const float* b2  = (const float*)d_in[7];
    const float* w2r = (const float*)d_in[8];
    const float* w3l = (const float*)d_in[9];
    const float* b3  = (const float*)d_in[10];
    const float* w3r = (const float*)d_in[11];
    const float* gate_w = (const float*)d_in[12];
    const float* gate_b = (const float*)d_in[13];
    const float* lin1_w = (const float*)d_in[14];
    const float* lin1_b = (const float*)d_in[15];
    const float* lin2_w = (const float*)d_in[16];
    const float* lin2_b = (const float*)d_in[17];
    float* out = (float*)d_out;

    const int TB = 256;

    // opt into >48KB dynamic smem (host-side attr set; idempotent, not a stream op)
    cudaFuncSetAttribute(k_layer, cudaFuncAttributeMaxDynamicSharedMemorySize,
                         LAYER_SMEM);

    k_init<<<(N_NODES + TB - 1) / TB, TB>>>(batch);
    k_hist<<<(N_EDGES + TB - 1) / TB, TB>>>(ei);
    k_scan_a<<<SCAN_NBLK, 256>>>();
    k_scan_b<<<1, 256>>>();
    k_scan_c<<<SCAN_NBLK, 256>>>();
    k_scatter<<<(N_EDGES + TB - 1) / TB, TB>>>(ei);

    int layer_blocks = (N_NODES + TILE_M - 1) / TILE_M;
    // layer 1: g_hA = relu(mean(x)@w1l + x@w1r + b1)
    k_layer<<<layer_blocks, 256, LAYER_SMEM>>>(x, w1l, w1r, b1, 0, N_NODES);
    // layer 2: g_hB = relu(mean(g_hA)@w2l + g_hA@w2r + b2)
    k_layer<<<layer_blocks, 256, LAYER_SMEM>>>(x, w2l, w2r, b2, 1, N_NODES);
    // layer 3: g_hA = relu(mean(g_hB)@w3l + g_hB@w3r + b3)
    k_layer<<<layer_blocks, 256, LAYER_SMEM>>>(x, w3l, w3r, b3, 2, N_NODES);

    // fused attentional aggregation + head
    k_attnpool<<<N_GRAPHS, 128>>>(gate_w, gate_b, lin1_w, lin1_b,
                                  lin2_w, lin2_b, out);
}

// round 9
// speedup vs baseline: 11.3568x; 11.3568x over previous
#include <cuda_runtime.h>
#include <cuda_bf16.h>
#include <math.h>

#define N_NODES   100000
#define N_EDGES   1600000
#define FEAT      128
#define N_GRAPHS  512
#define N_CLASSES 10

#define SCAN_ELEMS 512
#define SCAN_NBLK  ((N_NODES + SCAN_ELEMS - 1) / SCAN_ELEMS)   // 196

// ---------------- scratch (device globals; referenced ONLY from device code) --
__device__ int   g_deg[N_NODES];
__device__ int   g_off[N_NODES + 1];
__device__ int   g_cur[N_NODES];
__device__ int   g_csr[N_EDGES];
__device__ float g_cnt[N_NODES];
__device__ int   g_end[N_GRAPHS];
__device__ int   g_bsum[SCAN_NBLK];
__device__ int   g_bpre[SCAN_NBLK];

__device__ float g_mean[N_NODES * FEAT];
__device__ float g_hA[N_NODES * FEAT];
__device__ float g_hB[N_NODES * FEAT];
__device__ __align__(16) __nv_bfloat16 g_hb[N_NODES * FEAT];  // bf16 gather shadow
__device__ float g_gate[N_NODES];

// ---------------- helpers ----------------
__device__ __forceinline__ float tf32r(float x) {
    unsigned r;
    asm("cvt.rna.tf32.f32 %0, %1;" : "=r"(r) : "f"(x));
    return __uint_as_float(r);
}
__device__ __forceinline__ const float* sel_buf(int sel, const float* xext) {
    return sel == 0 ? xext : (sel == 1 ? (const float*)g_hA : (const float*)g_hB);
}
__device__ __forceinline__ void mma_tf32(float* d, const unsigned* a, const unsigned* b) {
    asm volatile(
        "mma.sync.aligned.m16n8k8.row.col.f32.tf32.tf32.f32 "
        "{%0,%1,%2,%3}, {%4,%5,%6,%7}, {%8,%9}, {%0,%1,%2,%3};"
        : "+f"(d[0]), "+f"(d[1]), "+f"(d[2]), "+f"(d[3])
        : "r"(a[0]), "r"(a[1]), "r"(a[2]), "r"(a[3]), "r"(b[0]), "r"(b[1]));
}

// ---------------- init: zero degrees + graph boundaries (verified R8) --------
__global__ void k_init(const int* __restrict__ batch) {
    int i = blockIdx.x * blockDim.x + threadIdx.x;
    if (i >= N_NODES) return;
    g_deg[i] = 0;
    int b  = batch[i];
    int bn = (i + 1 < N_NODES) ? batch[i + 1] : N_GRAPHS;
    if (i == 0)
        for (int g = 0; g < b; g++) g_end[g] = 0;
    for (int g = b; g < bn; g++) g_end[g] = i + 1;
}

// ---------------- CSR build (split layout: src=ei[0..E), dst=ei[E..2E)) ------
__global__ void k_hist(const int* __restrict__ ei) {
    int e = blockIdx.x * blockDim.x + threadIdx.x;
    if (e < N_EDGES) atomicAdd(&g_deg[ei[N_EDGES + e]], 1);
}

// parallel 3-phase exclusive scan (verified R8)
__global__ void k_scan_a() {
    int b = blockIdx.x, t = threadIdx.x;
    int i0 = b * SCAN_ELEMS + t * 2;
    int d0 = (i0 < N_NODES) ? g_deg[i0] : 0;
    int d1 = (i0 + 1 < N_NODES) ? g_deg[i0 + 1] : 0;
    __shared__ int sh[256];
    sh[t] = d0 + d1;
    __syncthreads();
    for (int s = 128; s > 0; s >>= 1) {
        if (t < s) sh[t] += sh[t + s];
        __syncthreads();
    }
    if (t == 0) g_bsum[b] = sh[0];
}
__global__ void k_scan_b() {
    int t = threadIdx.x;
    __shared__ int sh[256];
    int v = (t < SCAN_NBLK) ? g_bsum[t] : 0;
    sh[t] = v;
    __syncthreads();
    for (int d = 1; d < 256; d <<= 1) {
        int x = (t >= d) ? sh[t - d] : 0;
        __syncthreads();
        sh[t] += x;
        __syncthreads();
    }
    if (t < SCAN_NBLK) g_bpre[t] = sh[t] - v;
}
__global__ void k_scan_c() {
    int b = blockIdx.x, t = threadIdx.x;
    int i0 = b * SCAN_ELEMS + t * 2;
    int d0 = (i0 < N_NODES) ? g_deg[i0] : 0;
    int d1 = (i0 + 1 < N_NODES) ? g_deg[i0 + 1] : 0;
    __shared__ int sh[256];
    int v = d0 + d1;
    sh[t] = v;
    __syncthreads();
    for (int d = 1; d < 256; d <<= 1) {
        int x = (t >= d) ? sh[t - d] : 0;
        __syncthreads();
        sh[t] += x;
        __syncthreads();
    }
    int pre = g_bpre[b] + sh[t] - v;
    if (i0 < N_NODES) {
        g_off[i0] = pre; g_cur[i0] = pre;
        g_cnt[i0] = fmaxf((float)d0, 1.0f);
    }
    if (i0 + 1 < N_NODES) {
        g_off[i0 + 1] = pre + d0; g_cur[i0 + 1] = pre + d0;
        g_cnt[i0 + 1] = fmaxf((float)d1, 1.0f);
    }
    if (b == 0 && t == 0) g_off[N_NODES] = N_EDGES;
}

__global__ void k_scatter(const int* __restrict__ ei) {
    int e = blockIdx.x * blockDim.x + threadIdx.x;
    if (e < N_EDGES) {
        int pos = atomicAdd(&g_cur[ei[N_EDGES + e]], 1);
        g_csr[pos] = ei[e];
    }
}

// ---------------- x -> bf16 shadow --------------------------------------------
__global__ void k_conv(const float* __restrict__ x) {
    int i = blockIdx.x * blockDim.x + threadIdx.x;   // quad index
    if (i < N_NODES * FEAT / 4) {
        float4 v = __ldg((const float4*)x + i);
        __nv_bfloat162 a = __float22bfloat162_rn(make_float2(v.x, v.y));
        __nv_bfloat162 b = __float22bfloat162_rn(make_float2(v.z, v.w));
        uint2 o;
        o.x = *reinterpret_cast<unsigned*>(&a);
        o.y = *reinterpret_cast<unsigned*>(&b);
        *((uint2*)g_hb + i) = o;
    }
}

// ---------------- mean aggregation: warp per node, bf16 gather, unroll 4 -----
__global__ __launch_bounds__(256) void k_agg() {
    int node = (blockIdx.x * blockDim.x + threadIdx.x) >> 5;
    int lane = threadIdx.x & 31;
    if (node >= N_NODES) return;
    int s = g_off[node], e = g_off[node + 1];
    float ax = 0.f, ay = 0.f, az = 0.f, aw = 0.f;
    const uint2* base = (const uint2*)g_hb;          // 4 bf16 per uint2
    int i = s;
    for (; i + 4 <= e; i += 4) {
        int n0 = g_csr[i], n1 = g_csr[i + 1], n2 = g_csr[i + 2], n3 = g_csr[i + 3];
        uint2 r0 = __ldg(base + (size_t)n0 * (FEAT / 4) + lane);
        uint2 r1 = __ldg(base + (size_t)n1 * (FEAT / 4) + lane);
        uint2 r2 = __ldg(base + (size_t)n2 * (FEAT / 4) + lane);
        uint2 r3 = __ldg(base + (size_t)n3 * (FEAT / 4) + lane);
#define ACC4(r)  {                                                        \
        __nv_bfloat162 p0 = *reinterpret_cast<__nv_bfloat162*>(&(r).x);   \
        __nv_bfloat162 p1 = *reinterpret_cast<__nv_bfloat162*>(&(r).y);   \
        float2 f0 = __bfloat1622float2(p0);                               \
        float2 f1 = __bfloat1622float2(p1);                               \
        ax += f0.x; ay += f0.y; az += f1.x; aw += f1.y; }
        ACC4(r0) ACC4(r1) ACC4(r2) ACC4(r3)
    }
    for (; i < e; i++) {
        int n0 = g_csr[i];
        uint2 r0 = __ldg(base + (size_t)n0 * (FEAT / 4) + lane);
        ACC4(r0)
    }
#undef ACC4
    float inv = 1.0f / g_cnt[node];
    float4 o = make_float4(ax * inv, ay * inv, az * inv, aw * inv);
    *(float4*)(g_mean + (size_t)node * FEAT + lane * 4) = o;
}

// ---------------- tensor-core fused GEMM with register prefetch (R7) ---------
// out = relu(g_mean@W1 + A2@W2 + bias); also writes bf16 shadow if wb
#define GBM 128
#define GBK 32
__global__ __launch_bounds__(256) void k_gemm_tc(
    const float* __restrict__ xext,
    const float* __restrict__ W1, const float* __restrict__ W2,
    const float* __restrict__ bias, int sel, int wb, int nrows)
{
    const float* __restrict__ A2 = sel_buf(sel, xext);
    float* __restrict__ out = (sel == 1) ? g_hB : g_hA;
    const float* Aptr[2] = { (const float*)g_mean, A2 };
    const float* Wptr[2] = { W1, W2 };

    __shared__ float As[GBM][36];
    __shared__ float Bs[GBK][136];

    int row0 = blockIdx.x * GBM;
    int tid  = threadIdx.x;
    int lane = tid & 31;
    int wid  = tid >> 5;
    int wm   = wid & 3;
    int wn   = wid >> 2;

    int am = tid >> 3;
    int aq = (tid & 7) * 4;
    int brw = tid >> 5;
    int bc  = (tid & 31) * 4;

    float4 ar[4], brv[4];

    auto load_chunk = [&](int c) {
        int ph = c >> 2, k0 = (c & 3) * GBK;
        const float* __restrict__ A = Aptr[ph];
        const float* __restrict__ W = Wptr[ph];
#pragma unroll
        for (int p = 0; p < 4; p++) {
            int grow = row0 + am + p * 32;
            ar[p] = (grow < nrows)
                ? *(const float4*)(A + (size_t)grow * FEAT + k0 + aq)
                : make_float4(0.f, 0.f, 0.f, 0.f);
            brv[p] = *(const float4*)(W + (size_t)(k0 + brw + p * 8) * FEAT + bc);
        }
    };

    float d[2][8][4];
#pragma unroll
    for (int mt = 0; mt < 2; mt++)
#pragma unroll
        for (int nt = 0; nt < 8; nt++)
#pragma unroll
            for (int c = 0; c < 4; c++) d[mt][nt][c] = 0.0f;

    load_chunk(0);
    for (int c = 0; c < 8; c++) {
#pragma unroll
        for (int p = 0; p < 4; p++) {
            int row = am + p * 32;
            As[row][aq + 0] = tf32r(ar[p].x);
            As[row][aq + 1] = tf32r(ar[p].y);
            As[row][aq + 2] = tf32r(ar[p].z);
            As[row][aq + 3] = tf32r(ar[p].w);
            int krow = brw + p * 8;
            Bs[krow][bc + 0] = tf32r(brv[p].x);
            Bs[krow][bc + 1] = tf32r(brv[p].y);
            Bs[krow][bc + 2] = tf32r(brv[p].z);
            Bs[krow][bc + 3] = tf32r(brv[p].w);
        }
        __syncthreads();
        if (c < 7) load_chunk(c + 1);

#pragma unroll
        for (int ks = 0; ks < 4; ks++) {
            unsigned a[2][4], b[8][2];
            int arow = wm * 32 + (lane >> 2);
            int acol = ks * 8 + (lane & 3);
#pragma unroll
            for (int mt = 0; mt < 2; mt++) {
                int r0 = arow + mt * 16;
                a[mt][0] = __float_as_uint(As[r0][acol]);
                a[mt][1] = __float_as_uint(As[r0 + 8][acol]);
                a[mt][2] = __float_as_uint(As[r0][acol + 4]);
                a[mt][3] = __float_as_uint(As[r0 + 8][acol + 4]);
            }
            int bk  = ks * 8 + (lane & 3);
            int bn0 = wn * 64 + (lane >> 2);
#pragma unroll
            for (int nt = 0; nt < 8; nt++) {
                b[nt][0] = __float_as_uint(Bs[bk][bn0 + nt * 8]);
                b[nt][1] = __float_as_uint(Bs[bk + 4][bn0 + nt * 8]);
            }
#pragma unroll
            for (int mt = 0; mt < 2; mt++)
#pragma unroll
                for (int nt = 0; nt < 8; nt++)
                    mma_tf32(d[mt][nt], a[mt], b[nt]);
        }
        __syncthreads();
    }

    // ---- epilogue: bias + relu, fp32 + optional bf16 shadow ----
    int rbase = row0 + wm * 32 + (lane >> 2);
    int cbase = wn * 64 + (lane & 3) * 2;
#pragma unroll
    for (int nt = 0; nt < 8; nt++) {
        int col = cbase + nt * 8;
        float bv0 = __ldg(&bias[col]);
        float bv1 = __ldg(&bias[col + 1]);
#pragma unroll
        for (int mt = 0; mt < 2; mt++) {
            int r0 = rbase + mt * 16;
            if (r0 < nrows) {
                float2 o;
                o.x = fmaxf(d[mt][nt][0] + bv0, 0.0f);
                o.y = fmaxf(d[mt][nt][1] + bv1, 0.0f);
                *(float2*)(out + (size_t)r0 * FEAT + col) = o;
                if (wb)
                    *(__nv_bfloat162*)(g_hb + (size_t)r0 * FEAT + col) =
                        __float22bfloat162_rn(o);
            }
            int r1 = r0 + 8;
            if (r1 < nrows) {
                float2 o;
                o.x = fmaxf(d[mt][nt][2] + bv0, 0.0f);
                o.y = fmaxf(d[mt][nt][3] + bv1, 0.0f);
                *(float2*)(out + (size_t)r1 * FEAT + col) = o;
                if (wb)
                    *(__nv_bfloat162*)(g_hb + (size_t)r1 * FEAT + col) =
                        __float22bfloat162_rn(o);
            }
        }
    }
}

// ---------------- fused attention pooling + MLP head (1 block / graph) -------
__global__ __launch_bounds__(128) void k_attnpool(
    const float* __restrict__ gate_w, const float* __restrict__ gate_b,
    const float* __restrict__ lin1_w, const float* __restrict__ lin1_b,
    const float* __restrict__ lin2_w, const float* __restrict__ lin2_b,
    float* __restrict__ out)
{
    int g  = blockIdx.x;
    int lo = (g == 0) ? 0 : g_end[g - 1];
    int hi = g_end[g];
    int t = threadIdx.x, warp = t >> 5, lane = t & 31;

    __shared__ float red4[4];
    __shared__ float s_m, s_s;
    __shared__ float sp[FEAT];
    __shared__ float so[FEAT];
    __shared__ float lg[N_CLASSES];

    float4 wv = *(const float4*)(gate_w + lane * 4);
    float gb = __ldg(&gate_b[0]);
    float lmax = -1e30f;
    for (int node = lo + warp; node < hi; node += 4) {
        float4 hv = *(const float4*)(g_hA + (size_t)node * FEAT + lane * 4);
        float s = hv.x * wv.x + hv.y * wv.y + hv.z * wv.z + hv.w * wv.w;
#pragma unroll
        for (int d = 16; d > 0; d >>= 1) s += __shfl_xor_sync(0xFFFFFFFFu, s, d);
        s += gb;
        if (lane == 0) g_gate[node] = s;
        lmax = fmaxf(lmax, s);
    }
    if (lane == 0) red4[warp] = lmax;
    __syncthreads();
    if (t == 0)
        s_m = fmaxf(fmaxf(red4[0], red4[1]), fmaxf(red4[2], red4[3]));
    __syncthreads();
    float m = s_m;

    float part = 0.0f;
    for (int node = lo + t; node < hi; node += 128) {
        float e = expf(g_gate[node] - m);
        g_gate[node] = e;
        part += e;
    }
#pragma unroll
    for (int d = 16; d > 0; d >>= 1) part += __shfl_xor_sync(0xFFFFFFFFu, part, d);
    if (lane == 0) red4[warp] = part;
    __syncthreads();
    if (t == 0) s_s = red4[0] + red4[1] + red4[2] + red4[3];
    __syncthreads();
    float s = s_s;
    float invs = (s > 0.0f) ? 1.0f / s : 0.0f;

    float acc = 0.0f;
#pragma unroll 4
    for (int node = lo; node < hi; node++)
        acc += g_gate[node] * g_hA[(size_t)node * FEAT + t];
    sp[t] = acc * invs;
    __syncthreads();

    float h1 = lin1_b[t];
#pragma unroll 8
    for (int k = 0; k < FEAT; k++)
        h1 = fmaf(sp[k], lin1_w[(size_t)k * FEAT + t], h1);
    so[t] = fmaxf(h1, 0.0f);
    __syncthreads();

    if (t < N_CLASSES) {
        float a = lin2_b[t];
#pragma unroll 8
        for (int k = 0; k < FEAT; k++)
            a = fmaf(so[k], lin2_w[(size_t)k * N_CLASSES + t], a);
        lg[t] = a;
    }
    __syncthreads();

    if (t == 0) {
        float mx = lg[0];
#pragma unroll
        for (int j = 1; j < N_CLASSES; j++) mx = fmaxf(mx, lg[j]);
        float se = 0.0f;
#pragma unroll
        for (int j = 0; j < N_CLASSES; j++) se += expf(lg[j] - mx);
        float l = logf(se);
#pragma unroll
        for (int j = 0; j < N_CLASSES; j++)
            out[(size_t)g * N_CLASSES + j] = lg[j] - mx - l;
    }
}

// ---------------- launch ----------------
extern "C" void kernel_launch(void* const* d_in, const int* in_sizes, int n_in,
                              void* d_out, int out_size) {
    const float* x      = (const float*)d_in[0];
    const int*   ei     = (const int*)  d_in[1];
    const int*   batch  = (const int*)  d_in[2];
    const float* w1l = (const float*)d_in[3];
    const float* b1  = (const float*)d_in[4];
    const float* w1r = (const float*)d_in[5];
    const float* w2l = (const float*)d_in[6];
    const float* b2  = (const float*)d_in[7];
    const float* w2r = (const float*)d_in[8];
    const float* w3l = (const float*)d_in[9];
    const float* b3  = (const float*)d_in[10];
    const float* w3r = (const float*)d_in[11];
    const float* gate_w = (const float*)d_in[12];
    const float* gate_b = (const float*)d_in[13];
    const float* lin1_w = (const float*)d_in[14];
    const float* lin1_b = (const float*)d_in[15];
    const float* lin2_w = (const float*)d_in[16];
    const float* lin2_b = (const float*)d_in[17];
    float* out = (float*)d_out;

    const int TB = 256;

    k_init<<<(N_NODES + TB - 1) / TB, TB>>>(batch);
    k_hist<<<(N_EDGES + TB - 1) / TB, TB>>>(ei);
    k_conv<<<(N_NODES * FEAT / 4 + TB - 1) / TB, TB>>>(x);
    k_scan_a<<<SCAN_NBLK, 256>>>();
    k_scan_b<<<1, 256>>>();
    k_scan_c<<<SCAN_NBLK, 256>>>();
    k_scatter<<<(N_EDGES + TB - 1) / TB, TB>>>(ei);

    int agg_blocks  = (N_NODES * 32 + TB - 1) / TB;
    int gemm_blocks = (N_NODES + GBM - 1) / GBM;

    // layer 1: g_hA = relu(mean(x)@w1l + x@w1r + b1); shadow <- bf16(hA)
    k_agg<<<agg_blocks, TB>>>();
    k_gemm_tc<<<gemm_blocks, 256>>>(x, w1l, w1r, b1, 0, 1, N_NODES);
    // layer 2: g_hB = relu(mean(hA)@w2l + hA@w2r + b2); shadow <- bf16(hB)
    k_agg<<<agg_blocks, TB>>>();
    k_gemm_tc<<<gemm_blocks, 256>>>(x, w2l, w2r, b2, 1, 1, N_NODES);
    // layer 3: g_hA = relu(mean(hB)@w3l + hB@w3r + b3)
    k_agg<<<agg_blocks, TB>>>();
    k_gemm_tc<<<gemm_blocks, 256>>>(x, w3l, w3r, b3, 2, 0, N_NODES);

    // fused attentional aggregation + head
    k_attnpool<<<N_GRAPHS, 128>>>(gate_w, gate_b, lin1_w, lin1_b,
                                  lin2_w, lin2_b, out);
}

// round 10
// speedup vs baseline: 14.2275x; 1.2528x over previous
#include <cuda_runtime.h>
#include <cuda_bf16.h>
#include <math.h>

#define N_NODES   100000
#define N_EDGES   1600000
#define FEAT      128
#define N_GRAPHS  512
#define N_CLASSES 10

#define SCAN_ELEMS 512
#define SCAN_NBLK  ((N_NODES + SCAN_ELEMS - 1) / SCAN_ELEMS)   // 196

// ---------------- scratch (device globals; referenced ONLY from device code) --
__device__ int   g_deg[N_NODES];
__device__ int   g_off[N_NODES + 1];
__device__ int   g_cur[N_NODES];
__device__ int   g_csr[N_EDGES];
__device__ float g_cnt[N_NODES];
__device__ int   g_end[N_GRAPHS];
__device__ int   g_bsum[SCAN_NBLK];
__device__ int   g_bpre[SCAN_NBLK];

__device__ __align__(16) __nv_bfloat16 g_hb[N_NODES * FEAT];    // activation shadow (in-place across layers)
__device__ __align__(16) __nv_bfloat16 g_meanb[N_NODES * FEAT]; // bf16 neighbor-mean
__device__ float g_hA[N_NODES * FEAT];                          // fp32 final-layer output
__device__ float g_gate[N_NODES];

// ---------------- helpers ----------------
__device__ __forceinline__ float tf32r(float x) {
    unsigned r;
    asm("cvt.rna.tf32.f32 %0, %1;" : "=r"(r) : "f"(x));
    return __uint_as_float(r);
}
__device__ __forceinline__ void mma_tf32(float* d, const unsigned* a, const unsigned* b) {
    asm volatile(
        "mma.sync.aligned.m16n8k8.row.col.f32.tf32.tf32.f32 "
        "{%0,%1,%2,%3}, {%4,%5,%6,%7}, {%8,%9}, {%0,%1,%2,%3};"
        : "+f"(d[0]), "+f"(d[1]), "+f"(d[2]), "+f"(d[3])
        : "r"(a[0]), "r"(a[1]), "r"(a[2]), "r"(a[3]), "r"(b[0]), "r"(b[1]));
}
__device__ __forceinline__ void bf4_to_f4(uint2 r, float* o) {
    __nv_bfloat162 p0 = *reinterpret_cast<__nv_bfloat162*>(&r.x);
    __nv_bfloat162 p1 = *reinterpret_cast<__nv_bfloat162*>(&r.y);
    float2 f0 = __bfloat1622float2(p0);
    float2 f1 = __bfloat1622float2(p1);
    o[0] = f0.x; o[1] = f0.y; o[2] = f1.x; o[3] = f1.y;
}

// ---------------- setup: zero deg + boundaries + x -> bf16 shadow -------------
__global__ void k_setup(const float* __restrict__ x, const int* __restrict__ batch) {
    int i = blockIdx.x * blockDim.x + threadIdx.x;
    if (i < N_NODES * FEAT / 4) {
        float4 v = __ldg((const float4*)x + i);
        __nv_bfloat162 a = __float22bfloat162_rn(make_float2(v.x, v.y));
        __nv_bfloat162 b = __float22bfloat162_rn(make_float2(v.z, v.w));
        uint2 o;
        o.x = *reinterpret_cast<unsigned*>(&a);
        o.y = *reinterpret_cast<unsigned*>(&b);
        *((uint2*)g_hb + i) = o;
    }
    if (i < N_NODES) {
        g_deg[i] = 0;
        int b  = batch[i];
        int bn = (i + 1 < N_NODES) ? batch[i + 1] : N_GRAPHS;
        if (i == 0)
            for (int g = 0; g < b; g++) g_end[g] = 0;
        for (int g = b; g < bn; g++) g_end[g] = i + 1;
    }
}

// ---------------- CSR build (split layout: src=ei[0..E), dst=ei[E..2E)) ------
__global__ void k_hist(const int* __restrict__ ei) {
    int e = blockIdx.x * blockDim.x + threadIdx.x;
    if (e < N_EDGES) atomicAdd(&g_deg[ei[N_EDGES + e]], 1);
}

__global__ void k_scan_a() {
    int b = blockIdx.x, t = threadIdx.x;
    int i0 = b * SCAN_ELEMS + t * 2;
    int d0 = (i0 < N_NODES) ? g_deg[i0] : 0;
    int d1 = (i0 + 1 < N_NODES) ? g_deg[i0 + 1] : 0;
    __shared__ int sh[256];
    sh[t] = d0 + d1;
    __syncthreads();
    for (int s = 128; s > 0; s >>= 1) {
        if (t < s) sh[t] += sh[t + s];
        __syncthreads();
    }
    if (t == 0) g_bsum[b] = sh[0];
}
__global__ void k_scan_b() {
    int t = threadIdx.x;
    __shared__ int sh[256];
    int v = (t < SCAN_NBLK) ? g_bsum[t] : 0;
    sh[t] = v;
    __syncthreads();
    for (int d = 1; d < 256; d <<= 1) {
        int x = (t >= d) ? sh[t - d] : 0;
        __syncthreads();
        sh[t] += x;
        __syncthreads();
    }
    if (t < SCAN_NBLK) g_bpre[t] = sh[t] - v;
}
__global__ void k_scan_c() {
    int b = blockIdx.x, t = threadIdx.x;
    int i0 = b * SCAN_ELEMS + t * 2;
    int d0 = (i0 < N_NODES) ? g_deg[i0] : 0;
    int d1 = (i0 + 1 < N_NODES) ? g_deg[i0 + 1] : 0;
    __shared__ int sh[256];
    int v = d0 + d1;
    sh[t] = v;
    __syncthreads();
    for (int d = 1; d < 256; d <<= 1) {
        int x = (t >= d) ? sh[t - d] : 0;
        __syncthreads();
        sh[t] += x;
        __syncthreads();
    }
    int pre = g_bpre[b] + sh[t] - v;
    if (i0 < N_NODES) {
        g_off[i0] = pre; g_cur[i0] = pre;
        g_cnt[i0] = fmaxf((float)d0, 1.0f);
    }
    if (i0 + 1 < N_NODES) {
        g_off[i0 + 1] = pre + d0; g_cur[i0 + 1] = pre + d0;
        g_cnt[i0 + 1] = fmaxf((float)d1, 1.0f);
    }
    if (b == 0 && t == 0) g_off[N_NODES] = N_EDGES;
}

__global__ void k_scatter(const int* __restrict__ ei) {
    int e = blockIdx.x * blockDim.x + threadIdx.x;
    if (e < N_EDGES) {
        int pos = atomicAdd(&g_cur[ei[N_EDGES + e]], 1);
        g_csr[pos] = ei[e];
    }
}

// ---------------- mean aggregation: warp/node, bf16 in, bf16 out -------------
__global__ __launch_bounds__(256) void k_agg() {
    int node = (blockIdx.x * blockDim.x + threadIdx.x) >> 5;
    int lane = threadIdx.x & 31;
    if (node >= N_NODES) return;
    int s = g_off[node], e = g_off[node + 1];
    float ax = 0.f, ay = 0.f, az = 0.f, aw = 0.f;
    const uint2* base = (const uint2*)g_hb;
    int i = s;
    for (; i + 4 <= e; i += 4) {
        int n0 = g_csr[i], n1 = g_csr[i + 1], n2 = g_csr[i + 2], n3 = g_csr[i + 3];
        uint2 r0 = __ldg(base + (size_t)n0 * (FEAT / 4) + lane);
        uint2 r1 = __ldg(base + (size_t)n1 * (FEAT / 4) + lane);
        uint2 r2 = __ldg(base + (size_t)n2 * (FEAT / 4) + lane);
        uint2 r3 = __ldg(base + (size_t)n3 * (FEAT / 4) + lane);
        float f[4];
        bf4_to_f4(r0, f); ax += f[0]; ay += f[1]; az += f[2]; aw += f[3];
        bf4_to_f4(r1, f); ax += f[0]; ay += f[1]; az += f[2]; aw += f[3];
        bf4_to_f4(r2, f); ax += f[0]; ay += f[1]; az += f[2]; aw += f[3];
        bf4_to_f4(r3, f); ax += f[0]; ay += f[1]; az += f[2]; aw += f[3];
    }
    for (; i < e; i++) {
        int n0 = g_csr[i];
        uint2 r0 = __ldg(base + (size_t)n0 * (FEAT / 4) + lane);
        float f[4];
        bf4_to_f4(r0, f); ax += f[0]; ay += f[1]; az += f[2]; aw += f[3];
    }
    float inv = 1.0f / g_cnt[node];
    __nv_bfloat162 a = __float22bfloat162_rn(make_float2(ax * inv, ay * inv));
    __nv_bfloat162 b = __float22bfloat162_rn(make_float2(az * inv, aw * inv));
    uint2 o;
    o.x = *reinterpret_cast<unsigned*>(&a);
    o.y = *reinterpret_cast<unsigned*>(&b);
    *((uint2*)g_meanb + (size_t)node * (FEAT / 4) + lane) = o;
}

// ---------------- tensor-core fused GEMM, bf16 operands (A), tf32 weights ----
// result = relu(mean@W1 + h@W2 + bias)
// last=0: write bf16 shadow in place; last=1: write fp32 g_hA
#define GBM 128
#define GBK 32
__global__ __launch_bounds__(256) void k_gemm_tc(
    const float* __restrict__ W1, const float* __restrict__ W2,
    const float* __restrict__ bias, int last, int nrows)
{
    __shared__ float As[GBM][36];
    __shared__ float Bs[GBK][136];

    int row0 = blockIdx.x * GBM;
    int tid  = threadIdx.x;
    int lane = tid & 31;
    int wid  = tid >> 5;
    int wm   = wid & 3;
    int wn   = wid >> 2;

    int am = tid >> 3;             // 0..31 (A row base)
    int aq = (tid & 7) * 4;        // A col quad
    int brw = tid >> 5;            // 0..7
    int bc  = (tid & 31) * 4;

    uint2  ar[4];
    float4 brv[4];

    auto load_chunk = [&](int c) {
        int ph = c >> 2, k0 = (c & 3) * GBK;
        const uint2* __restrict__ Ab = ph ? (const uint2*)g_hb : (const uint2*)g_meanb;
        const float* __restrict__ W  = ph ? W2 : W1;
#pragma unroll
        for (int p = 0; p < 4; p++) {
            int grow = row0 + am + p * 32;
            ar[p] = (grow < nrows)
                ? __ldg(Ab + ((size_t)grow * FEAT + k0 + aq) / 4)
                : make_uint2(0u, 0u);
            brv[p] = *(const float4*)(W + (size_t)(k0 + brw + p * 8) * FEAT + bc);
        }
    };

    float d[2][8][4];
#pragma unroll
    for (int mt = 0; mt < 2; mt++)
#pragma unroll
        for (int nt = 0; nt < 8; nt++)
#pragma unroll
            for (int c = 0; c < 4; c++) d[mt][nt][c] = 0.0f;

    load_chunk(0);
    for (int c = 0; c < 8; c++) {
#pragma unroll
        for (int p = 0; p < 4; p++) {
            int row = am + p * 32;
            float f[4];
            bf4_to_f4(ar[p], f);           // bf16 subset of tf32: no cvt needed
            As[row][aq + 0] = f[0];
            As[row][aq + 1] = f[1];
            As[row][aq + 2] = f[2];
            As[row][aq + 3] = f[3];
            int krow = brw + p * 8;
            Bs[krow][bc + 0] = tf32r(brv[p].x);
            Bs[krow][bc + 1] = tf32r(brv[p].y);
            Bs[krow][bc + 2] = tf32r(brv[p].z);
            Bs[krow][bc + 3] = tf32r(brv[p].w);
        }
        __syncthreads();
        if (c < 7) load_chunk(c + 1);

#pragma unroll
        for (int ks = 0; ks < 4; ks++) {
            unsigned a[2][4], b[8][2];
            int arow = wm * 32 + (lane >> 2);
            int acol = ks * 8 + (lane & 3);
#pragma unroll
            for (int mt = 0; mt < 2; mt++) {
                int r0 = arow + mt * 16;
                a[mt][0] = __float_as_uint(As[r0][acol]);
                a[mt][1] = __float_as_uint(As[r0 + 8][acol]);
                a[mt][2] = __float_as_uint(As[r0][acol + 4]);
                a[mt][3] = __float_as_uint(As[r0 + 8][acol + 4]);
            }
            int bk  = ks * 8 + (lane & 3);
            int bn0 = wn * 64 + (lane >> 2);
#pragma unroll
            for (int nt = 0; nt < 8; nt++) {
                b[nt][0] = __float_as_uint(Bs[bk][bn0 + nt * 8]);
                b[nt][1] = __float_as_uint(Bs[bk + 4][bn0 + nt * 8]);
            }
#pragma unroll
            for (int mt = 0; mt < 2; mt++)
#pragma unroll
                for (int nt = 0; nt < 8; nt++)
                    mma_tf32(d[mt][nt], a[mt], b[nt]);
        }
        __syncthreads();
    }

    // ---- epilogue: bias + relu ----
    int rbase = row0 + wm * 32 + (lane >> 2);
    int cbase = wn * 64 + (lane & 3) * 2;
#pragma unroll
    for (int nt = 0; nt < 8; nt++) {
        int col = cbase + nt * 8;
        float bv0 = __ldg(&bias[col]);
        float bv1 = __ldg(&bias[col + 1]);
#pragma unroll
        for (int mt = 0; mt < 2; mt++) {
#pragma unroll
            for (int half = 0; half < 2; half++) {
                int r = rbase + mt * 16 + half * 8;
                if (r < nrows) {
                    float2 o;
                    o.x = fmaxf(d[mt][nt][half * 2 + 0] + bv0, 0.0f);
                    o.y = fmaxf(d[mt][nt][half * 2 + 1] + bv1, 0.0f);
                    if (last)
                        *(float2*)(g_hA + (size_t)r * FEAT + col) = o;
                    else
                        *(__nv_bfloat162*)(g_hb + (size_t)r * FEAT + col) =
                            __float22bfloat162_rn(o);
                }
            }
        }
    }
}

// ---------------- fused attention pooling + MLP head (1 block / graph) -------
__global__ __launch_bounds__(128) void k_attnpool(
    const float* __restrict__ gate_w, const float* __restrict__ gate_b,
    const float* __restrict__ lin1_w, const float* __restrict__ lin1_b,
    const float* __restrict__ lin2_w, const float* __restrict__ lin2_b,
    float* __restrict__ out)
{
    int g  = blockIdx.x;
    int lo = (g == 0) ? 0 : g_end[g - 1];
    int hi = g_end[g];
    int t = threadIdx.x, warp = t >> 5, lane = t & 31;

    __shared__ float red4[4];
    __shared__ float s_m, s_s;
    __shared__ float sp[FEAT];
    __shared__ float so[FEAT];
    __shared__ float lg[N_CLASSES];

    float4 wv = *(const float4*)(gate_w + lane * 4);
    float gb = __ldg(&gate_b[0]);
    float lmax = -1e30f;
    for (int node = lo + warp; node < hi; node += 4) {
        float4 hv = *(const float4*)(g_hA + (size_t)node * FEAT + lane * 4);
        float s = hv.x * wv.x + hv.y * wv.y + hv.z * wv.z + hv.w * wv.w;
#pragma unroll
        for (int d = 16; d > 0; d >>= 1) s += __shfl_xor_sync(0xFFFFFFFFu, s, d);
        s += gb;
        if (lane == 0) g_gate[node] = s;
        lmax = fmaxf(lmax, s);
    }
    if (lane == 0) red4[warp] = lmax;
    __syncthreads();
    if (t == 0)
        s_m = fmaxf(fmaxf(red4[0], red4[1]), fmaxf(red4[2], red4[3]));
    __syncthreads();
    float m = s_m;

    float part = 0.0f;
    for (int node = lo + t; node < hi; node += 128) {
        float e = expf(g_gate[node] - m);
        g_gate[node] = e;
        part += e;
    }
#pragma unroll
    for (int d = 16; d > 0; d >>= 1) part += __shfl_xor_sync(0xFFFFFFFFu, part, d);
    if (lane == 0) red4[warp] = part;
    __syncthreads();
    if (t == 0) s_s = red4[0] + red4[1] + red4[2] + red4[3];
    __syncthreads();
    float s = s_s;
    float invs = (s > 0.0f) ? 1.0f / s : 0.0f;

    float acc = 0.0f;
#pragma unroll 4
    for (int node = lo; node < hi; node++)
        acc += g_gate[node] * g_hA[(size_t)node * FEAT + t];
    sp[t] = acc * invs;
    __syncthreads();

    float h1 = lin1_b[t];
#pragma unroll 8
    for (int k = 0; k < FEAT; k++)
        h1 = fmaf(sp[k], lin1_w[(size_t)k * FEAT + t], h1);
    so[t] = fmaxf(h1, 0.0f);
    __syncthreads();

    if (t < N_CLASSES) {
        float a = lin2_b[t];
#pragma unroll 8
        for (int k = 0; k < FEAT; k++)
            a = fmaf(so[k], lin2_w[(size_t)k * N_CLASSES + t], a);
        lg[t] = a;
    }
    __syncthreads();

    if (t == 0) {
        float mx = lg[0];
#pragma unroll
        for (int j = 1; j < N_CLASSES; j++) mx = fmaxf(mx, lg[j]);
        float se = 0.0f;
#pragma unroll
        for (int j = 0; j < N_CLASSES; j++) se += expf(lg[j] - mx);
        float l = logf(se);
#pragma unroll
        for (int j = 0; j < N_CLASSES; j++)
            out[(size_t)g * N_CLASSES + j] = lg[j] - mx - l;
    }
}

// ---------------- launch ----------------
extern "C" void kernel_launch(void* const* d_in, const int* in_sizes, int n_in,
                              void* d_out, int out_size) {
    const float* x      = (const float*)d_in[0];
    const int*   ei     = (const int*)  d_in[1];
    const int*   batch  = (const int*)  d_in[2];
    const float* w1l = (const float*)d_in[3];
    const float* b1  = (const float*)d_in[4];
    const float* w1r = (const float*)d_in[5];
    const float* w2l = (const float*)d_in[6];
    const float* b2  = (const float*)d_in[7];
    const float* w2r = (const float*)d_in[8];
    const float* w3l = (const float*)d_in[9];
    const float* b3  = (const float*)d_in[10];
    const float* w3r = (const float*)d_in[11];
    const float* gate_w = (const float*)d_in[12];
    const float* gate_b = (const float*)d_in[13];
    const float* lin1_w = (const float*)d_in[14];
    const float* lin1_b = (const float*)d_in[15];
    const float* lin2_w = (const float*)d_in[16];
    const float* lin2_b = (const float*)d_in[17];
    float* out = (float*)d_out;

    const int TB = 256;

    k_setup<<<(N_NODES * FEAT / 4 + TB - 1) / TB, TB>>>(x, batch);
    k_hist<<<(N_EDGES + TB - 1) / TB, TB>>>(ei);
    k_scan_a<<<SCAN_NBLK, 256>>>();
    k_scan_b<<<1, 256>>>();
    k_scan_c<<<SCAN_NBLK, 256>>>();
    k_scatter<<<(N_EDGES + TB - 1) / TB, TB>>>(ei);

    int agg_blocks  = (N_NODES * 32 + TB - 1) / TB;
    int gemm_blocks = (N_NODES + GBM - 1) / GBM;

    // layer 1: shadow <- relu(mean(shadow)@w1l + shadow@w1r + b1)
    k_agg<<<agg_blocks, TB>>>();
    k_gemm_tc<<<gemm_blocks, 256>>>(w1l, w1r, b1, 0, N_NODES);
    // layer 2
    k_agg<<<agg_blocks, TB>>>();
    k_gemm_tc<<<gemm_blocks, 256>>>(w2l, w2r, b2, 0, N_NODES);
    // layer 3: fp32 out for pooling
    k_agg<<<agg_blocks, TB>>>();
    k_gemm_tc<<<gemm_blocks, 256>>>(w3l, w3r, b3, 1, N_NODES);

    // fused attentional aggregation + head
    k_attnpool<<<N_GRAPHS, 128>>>(gate_w, gate_b, lin1_w, lin1_b,
                                  lin2_w, lin2_b, out);
}